// round 2
// baseline (speedup 1.0000x reference)
#include <cuda_runtime.h>

#define BATCH 256
#define OUTF  1024
#define INF   1024

// fast-path invalid flag (0 = fast path OK) + phi scratch
__device__ int   g_flag;
__device__ float g_phi[BATCH * INF];

__global__ void init_kernel() { g_flag = 0; }

// Check scale/translation are uniform across the O dimension (row 0 == row o).
// If not, set g_flag -> general fallback path runs.
__global__ void check_kernel(const float4* __restrict__ scale,
                             const float4* __restrict__ trans) {
    int j = blockIdx.x * blockDim.x + threadIdx.x;   // 0 .. O*I/4-1
    int i4 = j & (INF / 4 - 1);                      // same column in row 0
    float4 s = scale[j], s0 = scale[i4];
    float4 t = trans[j], t0 = trans[i4];
    bool bad = (s.x != s0.x) | (s.y != s0.y) | (s.z != s0.z) | (s.w != s0.w) |
               (t.x != t0.x) | (t.y != t0.y) | (t.z != t0.z) | (t.w != t0.w);
    if (bad) atomicOr(&g_flag, 1);
}

__device__ __forceinline__ float dog(float x, float t, float s) {
    float z = (x - t) / s;
    return -z * __expf(-0.5f * z * z);
}

// Precompute phi(x) using row-0 scale/translation (valid when uniform across O)
__global__ void phi_kernel(const float4* __restrict__ x,
                           const float4* __restrict__ scale,
                           const float4* __restrict__ trans) {
    if (g_flag) return;
    int j = blockIdx.x * blockDim.x + threadIdx.x;   // 0 .. B*I/4-1
    int i4 = j & (INF / 4 - 1);
    float4 xv = x[j];
    float4 s = scale[i4];
    float4 t = trans[i4];
    float4 p;
    p.x = dog(xv.x, t.x, s.x);
    p.y = dog(xv.y, t.y, s.y);
    p.z = dog(xv.z, t.z, s.z);
    p.w = dog(xv.w, t.w, s.w);
    reinterpret_cast<float4*>(g_phi)[j] = p;
}

// out(B,O) = phi(B,I) @ W(O,I)^T  -- NT gemm, both operands K-major.
// BM=32 (batch), BN=64 (outf), BK=32. 128 threads, each computes 4x4.
#define BM 32
#define BN 64
#define BK 32

__global__ __launch_bounds__(128, 8)
void gemm_kernel(const float* __restrict__ w, float* __restrict__ out) {
    if (g_flag) return;

    __shared__ float As[BK][BM];       // [k][m]
    __shared__ float Bs[BK][BN];       // [k][n]

    int tid = threadIdx.x;             // 0..127
    int tx = tid & 15;                 // 0..15 -> n
    int ty = tid >> 4;                 // 0..7  -> m
    int m0 = blockIdx.y * BM;
    int n0 = blockIdx.x * BN;

    float acc[4][4] = {};

    for (int k0 = 0; k0 < INF; k0 += BK) {
        // load A tile: 32 rows x 8 float4-chunks = 256 chunks, 2 per thread
        #pragma unroll
        for (int c = tid; c < (BM * BK / 4); c += 128) {
            int row = c >> 3, kq = c & 7;
            float4 v = *reinterpret_cast<const float4*>(
                &g_phi[(m0 + row) * INF + k0 + kq * 4]);
            As[kq * 4 + 0][row] = v.x;
            As[kq * 4 + 1][row] = v.y;
            As[kq * 4 + 2][row] = v.z;
            As[kq * 4 + 3][row] = v.w;
        }
        // load B tile: 64 rows x 8 chunks = 512 chunks, 4 per thread
        #pragma unroll
        for (int c = tid; c < (BN * BK / 4); c += 128) {
            int row = c >> 3, kq = c & 7;
            float4 v = *reinterpret_cast<const float4*>(
                &w[(n0 + row) * INF + k0 + kq * 4]);
            Bs[kq * 4 + 0][row] = v.x;
            Bs[kq * 4 + 1][row] = v.y;
            Bs[kq * 4 + 2][row] = v.z;
            Bs[kq * 4 + 3][row] = v.w;
        }
        __syncthreads();

        #pragma unroll
        for (int k = 0; k < BK; ++k) {
            float4 a = *reinterpret_cast<float4*>(&As[k][ty * 4]);
            float4 b = *reinterpret_cast<float4*>(&Bs[k][tx * 4]);
            acc[0][0] += a.x * b.x; acc[0][1] += a.x * b.y;
            acc[0][2] += a.x * b.z; acc[0][3] += a.x * b.w;
            acc[1][0] += a.y * b.x; acc[1][1] += a.y * b.y;
            acc[1][2] += a.y * b.z; acc[1][3] += a.y * b.w;
            acc[2][0] += a.z * b.x; acc[2][1] += a.z * b.y;
            acc[2][2] += a.z * b.z; acc[2][3] += a.z * b.w;
            acc[3][0] += a.w * b.x; acc[3][1] += a.w * b.y;
            acc[3][2] += a.w * b.z; acc[3][3] += a.w * b.w;
        }
        __syncthreads();
    }

    #pragma unroll
    for (int r = 0; r < 4; ++r) {
        float4 v = make_float4(acc[r][0], acc[r][1], acc[r][2], acc[r][3]);
        *reinterpret_cast<float4*>(
            &out[(m0 + ty * 4 + r) * OUTF + n0 + tx * 4]) = v;
    }
}

// Exact general fallback (only runs if uniformity check failed)
__global__ void fallback_kernel(const float* __restrict__ x,
                                const float* __restrict__ w,
                                const float* __restrict__ s,
                                const float* __restrict__ t,
                                float* __restrict__ out) {
    if (!g_flag) return;
    int o = blockIdx.x * blockDim.x + threadIdx.x;  // 0..O-1
    int b = blockIdx.y;                             // 0..B-1
    const float* xr = x + b * INF;
    const float* wr = w + o * INF;
    const float* sr = s + o * INF;
    const float* tr = t + o * INF;
    float sum = 0.f;
    for (int i = 0; i < INF; ++i) {
        float z = (xr[i] - tr[i]) / sr[i];
        sum += wr[i] * (-z * __expf(-0.5f * z * z));
    }
    out[b * OUTF + o] = sum;
}

extern "C" void kernel_launch(void* const* d_in, const int* in_sizes, int n_in,
                              void* d_out, int out_size) {
    const float* x     = (const float*)d_in[0];
    const float* wgt   = (const float*)d_in[1];
    const float* scale = (const float*)d_in[2];
    const float* trans = (const float*)d_in[3];
    float* out = (float*)d_out;

    init_kernel<<<1, 1>>>();
    check_kernel<<<(OUTF * INF / 4) / 256, 256>>>(
        (const float4*)scale, (const float4*)trans);
    phi_kernel<<<(BATCH * INF / 4) / 256, 256>>>(
        (const float4*)x, (const float4*)scale, (const float4*)trans);
    gemm_kernel<<<dim3(OUTF / BN, BATCH / BM), 128>>>(wgt, out);
    fallback_kernel<<<dim3(OUTF / 256, BATCH), 256>>>(x, wgt, scale, trans, out);
}

// round 4
// speedup vs baseline: 2.0404x; 2.0404x over previous
#include <cuda_runtime.h>
#include <cuda_bf16.h>
#include <cstdint>

#define BATCH 256
#define OUTF  1024
#define INF   1024

// ---------------- device scratch (no allocs allowed) ----------------
__device__ int g_flag;
__device__ __nv_bfloat16 g_phi_hi[BATCH * INF];
__device__ __nv_bfloat16 g_phi_lo[BATCH * INF];
__device__ __nv_bfloat16 g_w_hi[OUTF * INF];
__device__ __nv_bfloat16 g_w_lo[OUTF * INF];

// ---------------- helpers ----------------
__device__ __forceinline__ uint32_t smem_u32(const void* p) {
    uint32_t a;
    asm("{ .reg .u64 t; cvta.to.shared.u64 t, %1; cvt.u32.u64 %0, t; }"
        : "=r"(a) : "l"(p));
    return a;
}

__device__ __forceinline__ void cp_async16(uint32_t dst, const void* src) {
    asm volatile("cp.async.cg.shared.global [%0], [%1], 16;"
                 :: "r"(dst), "l"(src) : "memory");
}
#define CP_COMMIT() asm volatile("cp.async.commit_group;" ::: "memory")
#define CP_WAIT(n)  asm volatile("cp.async.wait_group %0;" :: "n"(n) : "memory")

__device__ __forceinline__ void ldm_x4(uint32_t& r0, uint32_t& r1,
                                       uint32_t& r2, uint32_t& r3,
                                       uint32_t addr) {
    asm volatile("ldmatrix.sync.aligned.m8n8.x4.shared.b16 {%0,%1,%2,%3}, [%4];"
                 : "=r"(r0), "=r"(r1), "=r"(r2), "=r"(r3) : "r"(addr));
}

__device__ __forceinline__ void mma16816(float* c, const uint32_t* a,
                                         const uint32_t* b) {
    asm volatile(
        "mma.sync.aligned.m16n8k16.row.col.f32.bf16.bf16.f32 "
        "{%0,%1,%2,%3}, {%4,%5,%6,%7}, {%8,%9}, {%0,%1,%2,%3};"
        : "+f"(c[0]), "+f"(c[1]), "+f"(c[2]), "+f"(c[3])
        : "r"(a[0]), "r"(a[1]), "r"(a[2]), "r"(a[3]), "r"(b[0]), "r"(b[1]));
}

// ---------------- small kernels ----------------
__global__ void init_kernel() { g_flag = 0; }

__global__ void check_kernel(const float4* __restrict__ scale,
                             const float4* __restrict__ trans) {
    int j = blockIdx.x * blockDim.x + threadIdx.x;
    int i4 = j & (INF / 4 - 1);
    float4 s = scale[j], s0 = scale[i4];
    float4 t = trans[j], t0 = trans[i4];
    bool bad = (s.x != s0.x) | (s.y != s0.y) | (s.z != s0.z) | (s.w != s0.w) |
               (t.x != t0.x) | (t.y != t0.y) | (t.z != t0.z) | (t.w != t0.w);
    if (bad) atomicOr(&g_flag, 1);
}

__device__ __forceinline__ float dog(float x, float t, float s) {
    float z = (x - t) / s;
    return -z * __expf(-0.5f * z * z);
}

// phi(x) with row-0 scale/trans, split into bf16 hi/lo
__global__ void phi_kernel(const float4* __restrict__ x,
                           const float4* __restrict__ scale,
                           const float4* __restrict__ trans) {
    int j = blockIdx.x * blockDim.x + threadIdx.x;   // 0 .. B*I/4-1
    int i4 = j & (INF / 4 - 1);
    float4 xv = x[j];
    float4 s = scale[i4];
    float4 t = trans[i4];
    float4 p;
    p.x = dog(xv.x, t.x, s.x);
    p.y = dog(xv.y, t.y, s.y);
    p.z = dog(xv.z, t.z, s.z);
    p.w = dog(xv.w, t.w, s.w);
    __nv_bfloat162 h01 = __floats2bfloat162_rn(p.x, p.y);
    __nv_bfloat162 h23 = __floats2bfloat162_rn(p.z, p.w);
    __nv_bfloat162 l01 = __floats2bfloat162_rn(p.x - __bfloat162float(h01.x),
                                               p.y - __bfloat162float(h01.y));
    __nv_bfloat162 l23 = __floats2bfloat162_rn(p.z - __bfloat162float(h23.x),
                                               p.w - __bfloat162float(h23.y));
    reinterpret_cast<__nv_bfloat162*>(g_phi_hi)[2 * j]     = h01;
    reinterpret_cast<__nv_bfloat162*>(g_phi_hi)[2 * j + 1] = h23;
    reinterpret_cast<__nv_bfloat162*>(g_phi_lo)[2 * j]     = l01;
    reinterpret_cast<__nv_bfloat162*>(g_phi_lo)[2 * j + 1] = l23;
}

// W -> bf16 hi/lo split
__global__ void wconv_kernel(const float4* __restrict__ w) {
    int j = blockIdx.x * blockDim.x + threadIdx.x;   // 0 .. O*I/4-1
    float4 v = w[j];
    __nv_bfloat162 h01 = __floats2bfloat162_rn(v.x, v.y);
    __nv_bfloat162 h23 = __floats2bfloat162_rn(v.z, v.w);
    __nv_bfloat162 l01 = __floats2bfloat162_rn(v.x - __bfloat162float(h01.x),
                                               v.y - __bfloat162float(h01.y));
    __nv_bfloat162 l23 = __floats2bfloat162_rn(v.z - __bfloat162float(h23.x),
                                               v.w - __bfloat162float(h23.y));
    reinterpret_cast<__nv_bfloat162*>(g_w_hi)[2 * j]     = h01;
    reinterpret_cast<__nv_bfloat162*>(g_w_hi)[2 * j + 1] = h23;
    reinterpret_cast<__nv_bfloat162*>(g_w_lo)[2 * j]     = l01;
    reinterpret_cast<__nv_bfloat162*>(g_w_lo)[2 * j + 1] = l23;
}

// ---------------- split-bf16 mma.sync GEMM ----------------
// out(256,1024) = phi @ W^T via AhBh + AhBl + AlBh.
// CTA tile 32x64, grid (16,8) = 128 CTAs, 128 threads (4 warps, 2x2),
// warp tile 16x32. BK=64, 2-stage cp.async pipeline.
#define BM 32
#define BN 64
#define BK 64
#define NCHUNK (INF / BK)           // 16
// smem strides/sizes (bytes); row = 72 bf16 = 144B (pad 8 halves)
#define ROWB    144
#define A_TILE  (BM * ROWB)         // 4608
#define B_TILE  (BN * ROWB)         // 9216
#define STAGEB  (2 * A_TILE + 2 * B_TILE)   // 27648
#define GEMM_SMEM (2 * STAGEB)              // 55296

__global__ __launch_bounds__(128, 1)
void mma_gemm_kernel(float* __restrict__ out) {
    if (g_flag) return;
    extern __shared__ char dsm[];
    const uint32_t sb = smem_u32(dsm);

    const int tid = threadIdx.x;
    const int wid = tid >> 5, lid = tid & 31;
    const int wm = wid >> 1, wn = wid & 1;        // 2x2 warps
    const int m0 = blockIdx.y * BM;
    const int n0 = blockIdx.x * BN;

    const __nv_bfloat16* gAh = g_phi_hi;
    const __nv_bfloat16* gAl = g_phi_lo;
    const __nv_bfloat16* gBh = g_w_hi;
    const __nv_bfloat16* gBl = g_w_lo;

    // per-thread load slots: 1536 cp.async of 16B per chunk, 12 per thread
    // idx<512: A (hi/lo), else B (hi/lo)
    auto load_chunk = [&](int ci, int stage) {
        const int kc = ci * BK;
        const uint32_t st = sb + stage * STAGEB;
        #pragma unroll
        for (int it = 0; it < 12; it++) {
            int idx = tid + it * 128;
            if (idx < 512) {
                int tile = idx >> 8;            // 0=hi 1=lo
                int r = (idx >> 3) & 31;
                int s = idx & 7;
                const __nv_bfloat16* g = (tile ? gAl : gAh) +
                                         (size_t)(m0 + r) * INF + kc + s * 8;
                cp_async16(st + tile * A_TILE + r * ROWB + s * 16, g);
            } else {
                int idx2 = idx - 512;
                int tile = idx2 >> 9;
                int r = (idx2 >> 3) & 63;
                int s = idx2 & 7;
                const __nv_bfloat16* g = (tile ? gBl : gBh) +
                                         (size_t)(n0 + r) * INF + kc + s * 8;
                cp_async16(st + 2 * A_TILE + tile * B_TILE + r * ROWB + s * 16, g);
            }
        }
        CP_COMMIT();
    };

    float acc[4][4] = {};   // 4 n-blocks of 8, each 4 floats

    load_chunk(0, 0);

    // ldmatrix lane address components (element offsets within tile)
    const int a_row = wm * 16 + (lid & 15);
    const int a_colq = (lid >> 4) * 8;              // +0 / +8 in k
    const int b_row_base = wn * 32 + ((lid >> 4) * 8) + (lid & 7);
    const int b_colq = ((lid >> 3) & 1) * 8;

    for (int ci = 0; ci < NCHUNK; ci++) {
        if (ci + 1 < NCHUNK) load_chunk(ci + 1, (ci + 1) & 1);
        if (ci + 1 < NCHUNK) { CP_WAIT(1); } else { CP_WAIT(0); }
        __syncthreads();

        const uint32_t st = sb + (ci & 1) * STAGEB;
        const uint32_t sAh = st;
        const uint32_t sAl = st + A_TILE;
        const uint32_t sBh = st + 2 * A_TILE;
        const uint32_t sBl = st + 2 * A_TILE + B_TILE;

        #pragma unroll
        for (int ks = 0; ks < 4; ks++) {
            const int kb = ks * 16;
            uint32_t ah[4], al[4], bh[8], bl[8];
            ldm_x4(ah[0], ah[1], ah[2], ah[3],
                   sAh + a_row * ROWB + (kb + a_colq) * 2);
            ldm_x4(al[0], al[1], al[2], al[3],
                   sAl + a_row * ROWB + (kb + a_colq) * 2);
            #pragma unroll
            for (int nb16 = 0; nb16 < 2; nb16++) {
                ldm_x4(bh[nb16 * 4 + 0], bh[nb16 * 4 + 1],
                       bh[nb16 * 4 + 2], bh[nb16 * 4 + 3],
                       sBh + (b_row_base + nb16 * 16) * ROWB + (kb + b_colq) * 2);
                ldm_x4(bl[nb16 * 4 + 0], bl[nb16 * 4 + 1],
                       bl[nb16 * 4 + 2], bl[nb16 * 4 + 3],
                       sBl + (b_row_base + nb16 * 16) * ROWB + (kb + b_colq) * 2);
            }
            #pragma unroll
            for (int nb = 0; nb < 4; nb++) {
                mma16816(acc[nb], ah, &bh[nb * 2]);
                mma16816(acc[nb], ah, &bl[nb * 2]);
                mma16816(acc[nb], al, &bh[nb * 2]);
            }
        }
        __syncthreads();
    }

    // epilogue: direct STG.64 per c-frag half
    const int row0 = m0 + wm * 16 + (lid >> 2);
    const int col00 = n0 + wn * 32 + (lid & 3) * 2;
    #pragma unroll
    for (int nb = 0; nb < 4; nb++) {
        int col = col00 + nb * 8;
        *reinterpret_cast<float2*>(&out[(size_t)row0 * OUTF + col]) =
            make_float2(acc[nb][0], acc[nb][1]);
        *reinterpret_cast<float2*>(&out[(size_t)(row0 + 8) * OUTF + col]) =
            make_float2(acc[nb][2], acc[nb][3]);
    }
}

// ---------------- exact general fallback ----------------
__global__ void fallback_kernel(const float* __restrict__ x,
                                const float* __restrict__ w,
                                const float* __restrict__ s,
                                const float* __restrict__ t,
                                float* __restrict__ out) {
    if (!g_flag) return;
    int o = blockIdx.x * blockDim.x + threadIdx.x;
    int b = blockIdx.y;
    const float* xr = x + (size_t)b * INF;
    const float* wr = w + (size_t)o * INF;
    const float* sr = s + (size_t)o * INF;
    const float* tr = t + (size_t)o * INF;
    float sum = 0.f;
    for (int i = 0; i < INF; ++i) {
        float z = (xr[i] - tr[i]) / sr[i];
        sum += wr[i] * (-z * __expf(-0.5f * z * z));
    }
    out[(size_t)b * OUTF + o] = sum;
}

extern "C" void kernel_launch(void* const* d_in, const int* in_sizes, int n_in,
                              void* d_out, int out_size) {
    const float* x     = (const float*)d_in[0];
    const float* wgt   = (const float*)d_in[1];
    const float* scale = (const float*)d_in[2];
    const float* trans = (const float*)d_in[3];
    float* out = (float*)d_out;

    static bool attr_set = false;
    if (!attr_set) {
        cudaFuncSetAttribute(mma_gemm_kernel,
                             cudaFuncAttributeMaxDynamicSharedMemorySize,
                             GEMM_SMEM);
        attr_set = true;
    }

    init_kernel<<<1, 1>>>();
    check_kernel<<<(OUTF * INF / 4) / 256, 256>>>(
        (const float4*)scale, (const float4*)trans);
    phi_kernel<<<(BATCH * INF / 4) / 256, 256>>>(
        (const float4*)x, (const float4*)scale, (const float4*)trans);
    wconv_kernel<<<(OUTF * INF / 4) / 256, 256>>>((const float4*)wgt);
    mma_gemm_kernel<<<dim3(OUTF / BN, BATCH / BM), 128, GEMM_SMEM>>>(out);
    fallback_kernel<<<dim3(OUTF / 256, BATCH), 256>>>(x, wgt, scale, trans, out);
}

// round 5
// speedup vs baseline: 2.4374x; 1.1946x over previous
#include <cuda_runtime.h>
#include <cuda_bf16.h>
#include <cstdint>

#define BATCH 256
#define OUTF  1024
#define INF   1024

// ---------------- device scratch (no allocs allowed) ----------------
__device__ int g_flag;
__device__ __nv_bfloat16 g_phi_hi[BATCH * INF];
__device__ __nv_bfloat16 g_phi_lo[BATCH * INF];
__device__ __nv_bfloat16 g_w_hi[OUTF * INF];
__device__ __nv_bfloat16 g_w_lo[OUTF * INF];

// ---------------- helpers ----------------
__device__ __forceinline__ uint32_t smem_u32(const void* p) {
    uint32_t a;
    asm("{ .reg .u64 t; cvta.to.shared.u64 t, %1; cvt.u32.u64 %0, t; }"
        : "=r"(a) : "l"(p));
    return a;
}

__device__ __forceinline__ void cp_async16(uint32_t dst, const void* src) {
    asm volatile("cp.async.cg.shared.global [%0], [%1], 16;"
                 :: "r"(dst), "l"(src) : "memory");
}
#define CP_COMMIT() asm volatile("cp.async.commit_group;" ::: "memory")
#define CP_WAIT(n)  asm volatile("cp.async.wait_group %0;" :: "n"(n) : "memory")

__device__ __forceinline__ void ldm_x4(uint32_t& r0, uint32_t& r1,
                                       uint32_t& r2, uint32_t& r3,
                                       uint32_t addr) {
    asm volatile("ldmatrix.sync.aligned.m8n8.x4.shared.b16 {%0,%1,%2,%3}, [%4];"
                 : "=r"(r0), "=r"(r1), "=r"(r2), "=r"(r3) : "r"(addr));
}

__device__ __forceinline__ void mma16816(float* c, const uint32_t* a,
                                         const uint32_t* b) {
    asm volatile(
        "mma.sync.aligned.m16n8k16.row.col.f32.bf16.bf16.f32 "
        "{%0,%1,%2,%3}, {%4,%5,%6,%7}, {%8,%9}, {%0,%1,%2,%3};"
        : "+f"(c[0]), "+f"(c[1]), "+f"(c[2]), "+f"(c[3])
        : "r"(a[0]), "r"(a[1]), "r"(a[2]), "r"(a[3]), "r"(b[0]), "r"(b[1]));
}

// pack 8 floats -> uint4 of bf16 (hi) and uint4 of residual (lo)
__device__ __forceinline__ void split8(const float4& a, const float4& b,
                                       uint4& hi, uint4& lo) {
    __nv_bfloat162 h0 = __floats2bfloat162_rn(a.x, a.y);
    __nv_bfloat162 h1 = __floats2bfloat162_rn(a.z, a.w);
    __nv_bfloat162 h2 = __floats2bfloat162_rn(b.x, b.y);
    __nv_bfloat162 h3 = __floats2bfloat162_rn(b.z, b.w);
    __nv_bfloat162 l0 = __floats2bfloat162_rn(a.x - __bfloat162float(h0.x),
                                              a.y - __bfloat162float(h0.y));
    __nv_bfloat162 l1 = __floats2bfloat162_rn(a.z - __bfloat162float(h1.x),
                                              a.w - __bfloat162float(h1.y));
    __nv_bfloat162 l2 = __floats2bfloat162_rn(b.x - __bfloat162float(h2.x),
                                              b.y - __bfloat162float(h2.y));
    __nv_bfloat162 l3 = __floats2bfloat162_rn(b.z - __bfloat162float(h3.x),
                                              b.w - __bfloat162float(h3.y));
    hi = make_uint4(*(uint32_t*)&h0, *(uint32_t*)&h1,
                    *(uint32_t*)&h2, *(uint32_t*)&h3);
    lo = make_uint4(*(uint32_t*)&l0, *(uint32_t*)&l1,
                    *(uint32_t*)&l2, *(uint32_t*)&l3);
}

// ---------------- kernels ----------------
__global__ void init_kernel() { g_flag = 0; }

// Fused: uniformity check (scale/trans vs row 0) + W -> bf16 hi/lo split.
// One thread handles 8 consecutive floats (2 float4), MLP=6, 16B stores.
__global__ __launch_bounds__(256)
void prep_kernel(const float4* __restrict__ w,
                 const float4* __restrict__ scale,
                 const float4* __restrict__ trans) {
    int j = (blockIdx.x * blockDim.x + threadIdx.x) * 2;  // even float4 index
    int i40 = j & (INF / 4 - 1);
    int i41 = (j + 1) & (INF / 4 - 1);

    float4 w0 = w[j],     w1 = w[j + 1];
    float4 s0 = scale[j], s1 = scale[j + 1];
    float4 t0 = trans[j], t1 = trans[j + 1];
    float4 rs0 = scale[i40], rs1 = scale[i41];
    float4 rt0 = trans[i40], rt1 = trans[i41];

    bool bad =
        (s0.x != rs0.x) | (s0.y != rs0.y) | (s0.z != rs0.z) | (s0.w != rs0.w) |
        (s1.x != rs1.x) | (s1.y != rs1.y) | (s1.z != rs1.z) | (s1.w != rs1.w) |
        (t0.x != rt0.x) | (t0.y != rt0.y) | (t0.z != rt0.z) | (t0.w != rt0.w) |
        (t1.x != rt1.x) | (t1.y != rt1.y) | (t1.z != rt1.z) | (t1.w != rt1.w);
    if (bad) atomicOr(&g_flag, 1);

    uint4 hi, lo;
    split8(w0, w1, hi, lo);
    reinterpret_cast<uint4*>(g_w_hi)[j >> 1] = hi;
    reinterpret_cast<uint4*>(g_w_lo)[j >> 1] = lo;
}

__device__ __forceinline__ float dog(float x, float t, float s) {
    float z = (x - t) / s;
    return -z * __expf(-0.5f * z * z);
}

// phi(x) with row-0 scale/trans, split into bf16 hi/lo. 8 floats/thread.
__global__ __launch_bounds__(256)
void phi_kernel(const float4* __restrict__ x,
                const float4* __restrict__ scale,
                const float4* __restrict__ trans) {
    int j = (blockIdx.x * blockDim.x + threadIdx.x) * 2;  // even float4 index
    int i40 = j & (INF / 4 - 1);
    int i41 = (j + 1) & (INF / 4 - 1);
    float4 x0 = x[j], x1 = x[j + 1];
    float4 s0 = scale[i40], s1 = scale[i41];
    float4 t0 = trans[i40], t1 = trans[i41];
    float4 p0, p1;
    p0.x = dog(x0.x, t0.x, s0.x);
    p0.y = dog(x0.y, t0.y, s0.y);
    p0.z = dog(x0.z, t0.z, s0.z);
    p0.w = dog(x0.w, t0.w, s0.w);
    p1.x = dog(x1.x, t1.x, s1.x);
    p1.y = dog(x1.y, t1.y, s1.y);
    p1.z = dog(x1.z, t1.z, s1.z);
    p1.w = dog(x1.w, t1.w, s1.w);
    uint4 hi, lo;
    split8(p0, p1, hi, lo);
    reinterpret_cast<uint4*>(g_phi_hi)[j >> 1] = hi;
    reinterpret_cast<uint4*>(g_phi_lo)[j >> 1] = lo;
}

// ---------------- split-bf16 mma.sync GEMM (+ exact fallback branch) ----
// out(256,1024) = phi @ W^T via AhBh + AhBl + AlBh.
// CTA tile 32x64, grid (16,8) = 128 CTAs, 128 threads (4 warps, 2x2),
// warp tile 16x32. BK=64, 2-stage cp.async pipeline.
#define BM 32
#define BN 64
#define BK 64
#define NCHUNK (INF / BK)           // 16
#define ROWB    144                 // 72 bf16 per row (pad 8)
#define A_TILE  (BM * ROWB)         // 4608
#define B_TILE  (BN * ROWB)         // 9216
#define STAGEB  (2 * A_TILE + 2 * B_TILE)   // 27648
#define GEMM_SMEM (2 * STAGEB)              // 55296

__global__ __launch_bounds__(128, 1)
void mma_gemm_kernel(float* __restrict__ out,
                     const float* __restrict__ x,
                     const float* __restrict__ w,
                     const float* __restrict__ s,
                     const float* __restrict__ t) {
    const int tid = threadIdx.x;
    const int m0 = blockIdx.y * BM;
    const int n0 = blockIdx.x * BN;

    if (g_flag) {
        // exact general path: each thread computes 16 outputs of this tile
        for (int e = tid; e < BM * BN; e += 128) {
            int b = m0 + (e >> 6);
            int o = n0 + (e & 63);
            const float* xr = x + (size_t)b * INF;
            const float* wr = w + (size_t)o * INF;
            const float* sr = s + (size_t)o * INF;
            const float* tr = t + (size_t)o * INF;
            float sum = 0.f;
            for (int i = 0; i < INF; ++i) {
                float z = (xr[i] - tr[i]) / sr[i];
                sum += wr[i] * (-z * __expf(-0.5f * z * z));
            }
            out[(size_t)b * OUTF + o] = sum;
        }
        return;
    }

    extern __shared__ char dsm[];
    const uint32_t sb = smem_u32(dsm);

    const int wid = tid >> 5, lid = tid & 31;
    const int wm = wid >> 1, wn = wid & 1;        // 2x2 warps

    const __nv_bfloat16* gAh = g_phi_hi;
    const __nv_bfloat16* gAl = g_phi_lo;
    const __nv_bfloat16* gBh = g_w_hi;
    const __nv_bfloat16* gBl = g_w_lo;

    auto load_chunk = [&](int ci, int stage) {
        const int kc = ci * BK;
        const uint32_t st = sb + stage * STAGEB;
        #pragma unroll
        for (int it = 0; it < 12; it++) {
            int idx = tid + it * 128;
            if (idx < 512) {
                int tile = idx >> 8;            // 0=hi 1=lo
                int r = (idx >> 3) & 31;
                int q = idx & 7;
                const __nv_bfloat16* g = (tile ? gAl : gAh) +
                                         (size_t)(m0 + r) * INF + kc + q * 8;
                cp_async16(st + tile * A_TILE + r * ROWB + q * 16, g);
            } else {
                int idx2 = idx - 512;
                int tile = idx2 >> 9;
                int r = (idx2 >> 3) & 63;
                int q = idx2 & 7;
                const __nv_bfloat16* g = (tile ? gBl : gBh) +
                                         (size_t)(n0 + r) * INF + kc + q * 8;
                cp_async16(st + 2 * A_TILE + tile * B_TILE + r * ROWB + q * 16, g);
            }
        }
        CP_COMMIT();
    };

    float acc[4][4] = {};

    load_chunk(0, 0);

    const int a_row = wm * 16 + (lid & 15);
    const int a_colq = (lid >> 4) * 8;
    const int b_row_base = wn * 32 + ((lid >> 4) * 8) + (lid & 7);
    const int b_colq = ((lid >> 3) & 1) * 8;

    for (int ci = 0; ci < NCHUNK; ci++) {
        if (ci + 1 < NCHUNK) load_chunk(ci + 1, (ci + 1) & 1);
        if (ci + 1 < NCHUNK) { CP_WAIT(1); } else { CP_WAIT(0); }
        __syncthreads();

        const uint32_t st = sb + (ci & 1) * STAGEB;
        const uint32_t sAh = st;
        const uint32_t sAl = st + A_TILE;
        const uint32_t sBh = st + 2 * A_TILE;
        const uint32_t sBl = st + 2 * A_TILE + B_TILE;

        #pragma unroll
        for (int ks = 0; ks < 4; ks++) {
            const int kb = ks * 16;
            uint32_t ah[4], al[4], bh[8], bl[8];
            ldm_x4(ah[0], ah[1], ah[2], ah[3],
                   sAh + a_row * ROWB + (kb + a_colq) * 2);
            ldm_x4(al[0], al[1], al[2], al[3],
                   sAl + a_row * ROWB + (kb + a_colq) * 2);
            #pragma unroll
            for (int nb16 = 0; nb16 < 2; nb16++) {
                ldm_x4(bh[nb16 * 4 + 0], bh[nb16 * 4 + 1],
                       bh[nb16 * 4 + 2], bh[nb16 * 4 + 3],
                       sBh + (b_row_base + nb16 * 16) * ROWB + (kb + b_colq) * 2);
                ldm_x4(bl[nb16 * 4 + 0], bl[nb16 * 4 + 1],
                       bl[nb16 * 4 + 2], bl[nb16 * 4 + 3],
                       sBl + (b_row_base + nb16 * 16) * ROWB + (kb + b_colq) * 2);
            }
            #pragma unroll
            for (int nb = 0; nb < 4; nb++) {
                mma16816(acc[nb], ah, &bh[nb * 2]);
                mma16816(acc[nb], ah, &bl[nb * 2]);
                mma16816(acc[nb], al, &bh[nb * 2]);
            }
        }
        __syncthreads();
    }

    const int row0 = m0 + wm * 16 + (lid >> 2);
    const int col00 = n0 + wn * 32 + (lid & 3) * 2;
    #pragma unroll
    for (int nb = 0; nb < 4; nb++) {
        int col = col00 + nb * 8;
        *reinterpret_cast<float2*>(&out[(size_t)row0 * OUTF + col]) =
            make_float2(acc[nb][0], acc[nb][1]);
        *reinterpret_cast<float2*>(&out[(size_t)(row0 + 8) * OUTF + col]) =
            make_float2(acc[nb][2], acc[nb][3]);
    }
}

extern "C" void kernel_launch(void* const* d_in, const int* in_sizes, int n_in,
                              void* d_out, int out_size) {
    const float* x     = (const float*)d_in[0];
    const float* wgt   = (const float*)d_in[1];
    const float* scale = (const float*)d_in[2];
    const float* trans = (const float*)d_in[3];
    float* out = (float*)d_out;

    static bool attr_set = false;
    if (!attr_set) {
        cudaFuncSetAttribute(mma_gemm_kernel,
                             cudaFuncAttributeMaxDynamicSharedMemorySize,
                             GEMM_SMEM);
        attr_set = true;
    }

    init_kernel<<<1, 1>>>();
    // 8 floats per thread: O*I/8 threads = 131072 -> 512 blocks x 256
    prep_kernel<<<(OUTF * INF / 8) / 256, 256>>>(
        (const float4*)wgt, (const float4*)scale, (const float4*)trans);
    // B*I/8 threads = 32768 -> 128 blocks x 256
    phi_kernel<<<(BATCH * INF / 8) / 256, 256>>>(
        (const float4*)x, (const float4*)scale, (const float4*)trans);
    mma_gemm_kernel<<<dim3(OUTF / BN, BATCH / BM), 128, GEMM_SMEM>>>(
        out, x, wgt, scale, trans);
}

// round 6
// speedup vs baseline: 2.6933x; 1.1050x over previous
#include <cuda_runtime.h>
#include <cuda_bf16.h>
#include <cstdint>

#define BATCH 256
#define OUTF  1024
#define INF   1024

// ---------------- device scratch (no allocs allowed) ----------------
// g_flag is monotonic: stays 0 when scale/trans are O-uniform (fast path),
// else set to 1 by prep and every call takes the exact fallback. Either way
// behavior per call is deterministic for fixed inputs.
__device__ int g_flag = 0;
__device__ __nv_bfloat16 g_phi_hi[BATCH * INF];
__device__ __nv_bfloat16 g_phi_lo[BATCH * INF];
__device__ __nv_bfloat16 g_w_hi[OUTF * INF];
__device__ __nv_bfloat16 g_w_lo[OUTF * INF];

// ---------------- helpers ----------------
__device__ __forceinline__ uint32_t smem_u32(const void* p) {
    uint32_t a;
    asm("{ .reg .u64 t; cvta.to.shared.u64 t, %1; cvt.u32.u64 %0, t; }"
        : "=r"(a) : "l"(p));
    return a;
}

__device__ __forceinline__ void cp_async16(uint32_t dst, const void* src) {
    asm volatile("cp.async.cg.shared.global [%0], [%1], 16;"
                 :: "r"(dst), "l"(src) : "memory");
}
#define CP_COMMIT() asm volatile("cp.async.commit_group;" ::: "memory")
#define CP_WAIT(n)  asm volatile("cp.async.wait_group %0;" :: "n"(n) : "memory")

__device__ __forceinline__ void ldm_x4(uint32_t& r0, uint32_t& r1,
                                       uint32_t& r2, uint32_t& r3,
                                       uint32_t addr) {
    asm volatile("ldmatrix.sync.aligned.m8n8.x4.shared.b16 {%0,%1,%2,%3}, [%4];"
                 : "=r"(r0), "=r"(r1), "=r"(r2), "=r"(r3) : "r"(addr));
}

__device__ __forceinline__ void mma16816(float* c, const uint32_t* a,
                                         const uint32_t* b) {
    asm volatile(
        "mma.sync.aligned.m16n8k16.row.col.f32.bf16.bf16.f32 "
        "{%0,%1,%2,%3}, {%4,%5,%6,%7}, {%8,%9}, {%0,%1,%2,%3};"
        : "+f"(c[0]), "+f"(c[1]), "+f"(c[2]), "+f"(c[3])
        : "r"(a[0]), "r"(a[1]), "r"(a[2]), "r"(a[3]), "r"(b[0]), "r"(b[1]));
}

// pack 8 floats -> uint4 of bf16 (hi) and uint4 of residual (lo)
__device__ __forceinline__ void split8(const float4& a, const float4& b,
                                       uint4& hi, uint4& lo) {
    __nv_bfloat162 h0 = __floats2bfloat162_rn(a.x, a.y);
    __nv_bfloat162 h1 = __floats2bfloat162_rn(a.z, a.w);
    __nv_bfloat162 h2 = __floats2bfloat162_rn(b.x, b.y);
    __nv_bfloat162 h3 = __floats2bfloat162_rn(b.z, b.w);
    __nv_bfloat162 l0 = __floats2bfloat162_rn(a.x - __bfloat162float(h0.x),
                                              a.y - __bfloat162float(h0.y));
    __nv_bfloat162 l1 = __floats2bfloat162_rn(a.z - __bfloat162float(h1.x),
                                              a.w - __bfloat162float(h1.y));
    __nv_bfloat162 l2 = __floats2bfloat162_rn(b.x - __bfloat162float(h2.x),
                                              b.y - __bfloat162float(h2.y));
    __nv_bfloat162 l3 = __floats2bfloat162_rn(b.z - __bfloat162float(h3.x),
                                              b.w - __bfloat162float(h3.y));
    hi = make_uint4(*(uint32_t*)&h0, *(uint32_t*)&h1,
                    *(uint32_t*)&h2, *(uint32_t*)&h3);
    lo = make_uint4(*(uint32_t*)&l0, *(uint32_t*)&l1,
                    *(uint32_t*)&l2, *(uint32_t*)&l3);
}

__device__ __forceinline__ float dog(float x, float t, float s) {
    float z = (x - t) / s;
    return -z * __expf(-0.5f * z * z);
}

// ---------------- fused prep: check + W split + phi split ----------------
// Blocks [0, 512): W hi/lo split + uniformity check (8 floats/thread).
// Blocks [512, 640): phi(x) hi/lo split (8 floats/thread).
#define W_BLOCKS   ((OUTF * INF / 8) / 256)    // 512
#define PHI_BLOCKS ((BATCH * INF / 8) / 256)   // 128

__global__ __launch_bounds__(256)
void prep_kernel(const float4* __restrict__ w,
                 const float4* __restrict__ x,
                 const float4* __restrict__ scale,
                 const float4* __restrict__ trans) {
    if (blockIdx.x < W_BLOCKS) {
        int j = (blockIdx.x * 256 + threadIdx.x) * 2;  // even float4 index
        int i40 = j & (INF / 4 - 1);
        int i41 = (j + 1) & (INF / 4 - 1);

        float4 w0 = w[j],     w1 = w[j + 1];
        float4 s0 = scale[j], s1 = scale[j + 1];
        float4 t0 = trans[j], t1 = trans[j + 1];
        float4 rs0 = scale[i40], rs1 = scale[i41];
        float4 rt0 = trans[i40], rt1 = trans[i41];

        bool bad =
            (s0.x != rs0.x) | (s0.y != rs0.y) | (s0.z != rs0.z) | (s0.w != rs0.w) |
            (s1.x != rs1.x) | (s1.y != rs1.y) | (s1.z != rs1.z) | (s1.w != rs1.w) |
            (t0.x != rt0.x) | (t0.y != rt0.y) | (t0.z != rt0.z) | (t0.w != rt0.w) |
            (t1.x != rt1.x) | (t1.y != rt1.y) | (t1.z != rt1.z) | (t1.w != rt1.w);
        if (bad) atomicOr(&g_flag, 1);

        uint4 hi, lo;
        split8(w0, w1, hi, lo);
        reinterpret_cast<uint4*>(g_w_hi)[j >> 1] = hi;
        reinterpret_cast<uint4*>(g_w_lo)[j >> 1] = lo;
    } else {
        int j = ((blockIdx.x - W_BLOCKS) * 256 + threadIdx.x) * 2;
        int i40 = j & (INF / 4 - 1);
        int i41 = (j + 1) & (INF / 4 - 1);
        float4 x0 = x[j], x1 = x[j + 1];
        float4 s0 = scale[i40], s1 = scale[i41];
        float4 t0 = trans[i40], t1 = trans[i41];
        float4 p0, p1;
        p0.x = dog(x0.x, t0.x, s0.x);
        p0.y = dog(x0.y, t0.y, s0.y);
        p0.z = dog(x0.z, t0.z, s0.z);
        p0.w = dog(x0.w, t0.w, s0.w);
        p1.x = dog(x1.x, t1.x, s1.x);
        p1.y = dog(x1.y, t1.y, s1.y);
        p1.z = dog(x1.z, t1.z, s1.z);
        p1.w = dog(x1.w, t1.w, s1.w);
        uint4 hi, lo;
        split8(p0, p1, hi, lo);
        reinterpret_cast<uint4*>(g_phi_hi)[j >> 1] = hi;
        reinterpret_cast<uint4*>(g_phi_lo)[j >> 1] = lo;
    }
}

// ---------------- split-bf16 mma.sync GEMM (+ exact fallback branch) ----
// out(256,1024) = phi @ W^T via AhBh + AhBl + AlBh.
// CTA tile 32x32, grid (32,8) = 256 CTAs (2 per SM), 128 threads
// (4 warps, 2x2), warp tile 16x16. BK=64, 2-stage cp.async pipeline.
#define BM 32
#define BN 32
#define BK 64
#define NCHUNK (INF / BK)           // 16
#define ROWB    144                 // 72 bf16 per row (pad 8)
#define A_TILE  (BM * ROWB)         // 4608
#define B_TILE  (BN * ROWB)         // 4608
#define STAGEB  (2 * A_TILE + 2 * B_TILE)   // 18432
#define GEMM_SMEM (2 * STAGEB)              // 36864

__global__ __launch_bounds__(128, 2)
void mma_gemm_kernel(float* __restrict__ out,
                     const float* __restrict__ x,
                     const float* __restrict__ w,
                     const float* __restrict__ s,
                     const float* __restrict__ t) {
    const int tid = threadIdx.x;
    const int m0 = blockIdx.y * BM;
    const int n0 = blockIdx.x * BN;

    if (g_flag) {
        // exact general path: each thread computes 8 outputs of this tile
        for (int e = tid; e < BM * BN; e += 128) {
            int b = m0 + (e >> 5);
            int o = n0 + (e & 31);
            const float* xr = x + (size_t)b * INF;
            const float* wr = w + (size_t)o * INF;
            const float* sr = s + (size_t)o * INF;
            const float* tr = t + (size_t)o * INF;
            float sum = 0.f;
            for (int i = 0; i < INF; ++i) {
                float z = (xr[i] - tr[i]) / sr[i];
                sum += wr[i] * (-z * __expf(-0.5f * z * z));
            }
            out[(size_t)b * OUTF + o] = sum;
        }
        return;
    }

    extern __shared__ char dsm[];
    const uint32_t sb = smem_u32(dsm);

    const int wid = tid >> 5, lid = tid & 31;
    const int wm = wid >> 1, wn = wid & 1;        // 2x2 warps, tile 16x16

    const __nv_bfloat16* gAh = g_phi_hi;
    const __nv_bfloat16* gAl = g_phi_lo;
    const __nv_bfloat16* gBh = g_w_hi;
    const __nv_bfloat16* gBl = g_w_lo;

    // 1024 cp.async slots per chunk, 8 per thread
    auto load_chunk = [&](int ci, int stage) {
        const int kc = ci * BK;
        const uint32_t st = sb + stage * STAGEB;
        #pragma unroll
        for (int it = 0; it < 8; it++) {
            int idx = tid + it * 128;
            if (idx < 512) {
                int tile = idx >> 8;            // 0=hi 1=lo
                int r = (idx >> 3) & 31;
                int q = idx & 7;
                const __nv_bfloat16* g = (tile ? gAl : gAh) +
                                         (size_t)(m0 + r) * INF + kc + q * 8;
                cp_async16(st + tile * A_TILE + r * ROWB + q * 16, g);
            } else {
                int idx2 = idx - 512;
                int tile = idx2 >> 8;
                int r = (idx2 >> 3) & 31;
                int q = idx2 & 7;
                const __nv_bfloat16* g = (tile ? gBl : gBh) +
                                         (size_t)(n0 + r) * INF + kc + q * 8;
                cp_async16(st + 2 * A_TILE + tile * B_TILE + r * ROWB + q * 16, g);
            }
        }
        CP_COMMIT();
    };

    float acc[2][4] = {};

    load_chunk(0, 0);

    const int a_row = wm * 16 + (lid & 15);
    const int a_colq = (lid >> 4) * 8;
    const int b_row = wn * 16 + ((lid >> 4) * 8) + (lid & 7);
    const int b_colq = ((lid >> 3) & 1) * 8;

    for (int ci = 0; ci < NCHUNK; ci++) {
        if (ci + 1 < NCHUNK) load_chunk(ci + 1, (ci + 1) & 1);
        if (ci + 1 < NCHUNK) { CP_WAIT(1); } else { CP_WAIT(0); }
        __syncthreads();

        const uint32_t st = sb + (ci & 1) * STAGEB;
        const uint32_t sAh = st;
        const uint32_t sAl = st + A_TILE;
        const uint32_t sBh = st + 2 * A_TILE;
        const uint32_t sBl = st + 2 * A_TILE + B_TILE;

        #pragma unroll
        for (int ks = 0; ks < 4; ks++) {
            const int kb = ks * 16;
            uint32_t ah[4], al[4], bh[4], bl[4];
            ldm_x4(ah[0], ah[1], ah[2], ah[3],
                   sAh + a_row * ROWB + (kb + a_colq) * 2);
            ldm_x4(al[0], al[1], al[2], al[3],
                   sAl + a_row * ROWB + (kb + a_colq) * 2);
            ldm_x4(bh[0], bh[1], bh[2], bh[3],
                   sBh + b_row * ROWB + (kb + b_colq) * 2);
            ldm_x4(bl[0], bl[1], bl[2], bl[3],
                   sBl + b_row * ROWB + (kb + b_colq) * 2);
            #pragma unroll
            for (int nb = 0; nb < 2; nb++) {
                mma16816(acc[nb], ah, &bh[nb * 2]);
                mma16816(acc[nb], ah, &bl[nb * 2]);
                mma16816(acc[nb], al, &bh[nb * 2]);
            }
        }
        __syncthreads();
    }

    const int row0 = m0 + wm * 16 + (lid >> 2);
    const int col00 = n0 + wn * 16 + (lid & 3) * 2;
    #pragma unroll
    for (int nb = 0; nb < 2; nb++) {
        int col = col00 + nb * 8;
        *reinterpret_cast<float2*>(&out[(size_t)row0 * OUTF + col]) =
            make_float2(acc[nb][0], acc[nb][1]);
        *reinterpret_cast<float2*>(&out[(size_t)(row0 + 8) * OUTF + col]) =
            make_float2(acc[nb][2], acc[nb][3]);
    }
}

extern "C" void kernel_launch(void* const* d_in, const int* in_sizes, int n_in,
                              void* d_out, int out_size) {
    const float* x     = (const float*)d_in[0];
    const float* wgt   = (const float*)d_in[1];
    const float* scale = (const float*)d_in[2];
    const float* trans = (const float*)d_in[3];
    float* out = (float*)d_out;

    static bool attr_set = false;
    if (!attr_set) {
        cudaFuncSetAttribute(mma_gemm_kernel,
                             cudaFuncAttributeMaxDynamicSharedMemorySize,
                             GEMM_SMEM);
        attr_set = true;
    }

    prep_kernel<<<W_BLOCKS + PHI_BLOCKS, 256>>>(
        (const float4*)wgt, (const float4*)x,
        (const float4*)scale, (const float4*)trans);
    mma_gemm_kernel<<<dim3(OUTF / BN, BATCH / BM), 128, GEMM_SMEM>>>(
        out, x, wgt, scale, trans);
}